// round 8
// baseline (speedup 1.0000x reference)
#include <cuda_runtime.h>
#include <cuda_fp16.h>
#include <math_constants.h>
#include <cstdint>

#define B_ 8
#define C_ 256
#define N_ 2048
#define SCALE 0.0625f  // 1/sqrt(256)

// ------------------------- fp16 scratch (device globals) -------------------
__device__ __align__(16) __half g_q16[(size_t)B_ * C_ * N_];
__device__ __align__(16) __half g_k16[(size_t)B_ * C_ * N_];
__device__ __align__(16) __half g_v16[(size_t)B_ * C_ * N_];
__device__ __align__(16) __half g_w16[(size_t)B_ * N_ * N_];

// ------------------------------ PTX helpers --------------------------------
__device__ __forceinline__ uint32_t smem_u32(const void* p) {
    uint32_t a;
    asm("{ .reg .u64 t; cvta.to.shared.u64 t, %1; cvt.u32.u64 %0, t; }"
        : "=r"(a) : "l"(p));
    return a;
}
__device__ __forceinline__ void cp16(uint32_t dst, const void* src) {
    asm volatile("cp.async.cg.shared.global [%0], [%1], 16;" :: "r"(dst), "l"(src));
}
#define CP_COMMIT() asm volatile("cp.async.commit_group;" ::: "memory")
#define CP_WAIT2()  asm volatile("cp.async.wait_group 2;" ::: "memory")

#define LDSM4(r0, r1, r2, r3, a)                                               \
    asm volatile("ldmatrix.sync.aligned.m8n8.x4.shared.b16 {%0,%1,%2,%3},[%4];"\
                 : "=r"(r0), "=r"(r1), "=r"(r2), "=r"(r3) : "r"(a))
#define LDSM4T(r0, r1, r2, r3, a)                                              \
    asm volatile("ldmatrix.sync.aligned.m8n8.x4.trans.shared.b16 "             \
                 "{%0,%1,%2,%3},[%4];"                                         \
                 : "=r"(r0), "=r"(r1), "=r"(r2), "=r"(r3) : "r"(a))

__device__ __forceinline__ void mma_f16(float4& d, const uint32_t a[4],
                                        uint32_t b0, uint32_t b1) {
    asm volatile(
        "mma.sync.aligned.m16n8k16.row.col.f32.f16.f16.f32 "
        "{%0,%1,%2,%3}, {%4,%5,%6,%7}, {%8,%9}, {%0,%1,%2,%3};"
        : "+f"(d.x), "+f"(d.y), "+f"(d.z), "+f"(d.w)
        : "r"(a[0]), "r"(a[1]), "r"(a[2]), "r"(a[3]), "r"(b0), "r"(b1));
}

// ============================================================================
// fp32 -> fp16 convert, all three tensors in one launch (blockIdx.y selects).
// ============================================================================
__global__ __launch_bounds__(256)
void cvt16_all(const float* __restrict__ q, const float* __restrict__ k,
               const float* __restrict__ v)
{
    const float* s = (blockIdx.y == 0) ? q : (blockIdx.y == 1) ? k : v;
    __half* d = (blockIdx.y == 0) ? g_q16 : (blockIdx.y == 1) ? g_k16 : g_v16;
    size_t i = ((size_t)blockIdx.x * 256 + threadIdx.x) * 4;
    float4 x = *(const float4*)(s + i);
    *(__half2*)(d + i)     = __floats2half2_rn(x.x, x.y);
    *(__half2*)(d + i + 2) = __floats2half2_rn(x.z, x.w);
}

// ============================================================================
// fp16 GEMM, cp.async + ldmatrix + mma.m16n8k16.
//   MODE 1 (gemm1): D[b,i,j] = SCALE * sum_c K16(c,i) * Q16(c,j)
//                   also writes fp16 logits to g_w16.
//   MODE 2 (gemm2): D[b,c,j] = sum_i V16(c,i) * W16(i,j)
// CTA 128x128, 256 thr = 8 warps (2x4), warp 64x32, BK=16, 4-stage cp.async.
// ============================================================================
template <int MODE>
__global__ __launch_bounds__(256, 2)
void gemm_f16(float* __restrict__ Dg)
{
    __shared__ __align__(256) uint8_t smem[4 * 8192];
    const uint32_t sb = smem_u32(smem);

    const __half* Ag = (MODE == 1) ? g_k16 : g_v16;
    const __half* Bg = (MODE == 1) ? g_q16 : g_w16;
    const size_t batchA = (size_t)C_ * N_;
    const size_t batchB = (MODE == 1) ? (size_t)C_ * N_ : (size_t)N_ * N_;
    const size_t batchD = (MODE == 1) ? (size_t)N_ * N_ : (size_t)C_ * N_;
    const int Ktot = (MODE == 1) ? C_ : N_;
    const float sc = (MODE == 1) ? SCALE : 1.0f;

    const int tid  = threadIdx.x;
    const int w    = tid >> 5;
    const int lane = tid & 31;
    const int qr   = lane >> 2;
    const int qc   = lane & 3;
    const int g2   = lane >> 3;
    const int tr   = lane & 7;
    const int wm   = (w >> 2) * 64;
    const int wn   = (w & 3) * 32;
    const int m0   = blockIdx.y * 128;
    const int j0   = blockIdx.x * 128;

    const __half* A  = Ag + (size_t)blockIdx.z * batchA;
    const __half* Bp = Bg + (size_t)blockIdx.z * batchB;
    float* Dp = Dg + (size_t)blockIdx.z * batchD;

    float4 acc[4][4];
#pragma unroll
    for (int mt = 0; mt < 4; mt++)
#pragma unroll
        for (int nt = 0; nt < 4; nt++)
            acc[mt][nt] = make_float4(0.f, 0.f, 0.f, 0.f);

    // ---- cp.async mapping ----
    const int brow = tid >> 4, bch = tid & 15;
    const uint32_t bdst = (uint32_t)brow * 256 + (uint32_t)((bch ^ (brow & 7)) << 4);
    const int arow2 = tid >> 1, ach2 = tid & 1;
    const uint32_t adst2 = (uint32_t)arow2 * 32 +
                           (uint32_t)((ach2 ^ ((arow2 >> 2) & 1)) << 4);

    auto issue = [&](int s) {
        const uint32_t bb = sb + (uint32_t)(s & 3) * 8192;
        const int k0 = s << 4;
        if (MODE == 1) {
            cp16(bb + bdst, A + (size_t)(k0 + brow) * N_ + m0 + bch * 8);
        } else {
            cp16(bb + adst2, A + (size_t)(m0 + arow2) * N_ + k0 + ach2 * 8);
        }
        cp16(bb + 4096 + bdst, Bp + (size_t)(k0 + brow) * N_ + j0 + bch * 8);
    };

    const int S = Ktot >> 4;
    issue(0); CP_COMMIT();
    issue(1); CP_COMMIT();
    issue(2); CP_COMMIT();

    // ---- ldmatrix address precompute ----
    uint32_t aoff[4], boff[2];
    if (MODE == 1) {
        const int kr = tr + ((g2 >> 1) << 3);
#pragma unroll
        for (int mt = 0; mt < 4; mt++) {
            const int ch = ((wm + mt * 16) >> 3) + (g2 & 1);
            aoff[mt] = (uint32_t)kr * 256 + (uint32_t)((ch ^ (kr & 7)) << 4);
        }
    } else {
#pragma unroll
        for (int mt = 0; mt < 4; mt++) {
            const int mr = wm + mt * 16 + tr + ((g2 & 1) << 3);
            const int ch = (g2 >> 1) ^ ((mr >> 2) & 1);
            aoff[mt] = (uint32_t)mr * 32 + (uint32_t)(ch << 4);
        }
    }
    {
        const int kr = tr + ((g2 & 1) << 3);
#pragma unroll
        for (int p = 0; p < 2; p++) {
            const int ch = ((wn + p * 16) >> 3) + (g2 >> 1);
            boff[p] = 4096u + (uint32_t)kr * 256 + (uint32_t)((ch ^ (kr & 7)) << 4);
        }
    }

#pragma unroll 1
    for (int s = 0; s < S; s++) {
        CP_WAIT2();
        __syncthreads();      // single barrier per stage (buffer s-1 reads done)
        if (s + 3 < S) issue(s + 3);
        CP_COMMIT();

        const uint32_t bb = sb + (uint32_t)(s & 3) * 8192;

        uint32_t bf[2][4];
#pragma unroll
        for (int p = 0; p < 2; p++)
            LDSM4T(bf[p][0], bf[p][1], bf[p][2], bf[p][3], bb + boff[p]);

#pragma unroll
        for (int mt = 0; mt < 4; mt++) {
            uint32_t af[4];
            if (MODE == 1) { LDSM4T(af[0], af[1], af[2], af[3], bb + aoff[mt]); }
            else           { LDSM4 (af[0], af[1], af[2], af[3], bb + aoff[mt]); }
#pragma unroll
            for (int p = 0; p < 2; p++) {
                mma_f16(acc[mt][p * 2],     af, bf[p][0], bf[p][1]);
                mma_f16(acc[mt][p * 2 + 1], af, bf[p][2], bf[p][3]);
            }
        }
    }

    // ---------------- epilogue ----------------
    __half* Hp = g_w16 + (size_t)blockIdx.z * ((size_t)N_ * N_);
#pragma unroll
    for (int mt = 0; mt < 4; mt++) {
        const int r0 = m0 + wm + mt * 16 + qr;
#pragma unroll
        for (int nt = 0; nt < 4; nt++) {
            const int c0 = j0 + wn + nt * 8 + qc * 2;
            float2 v0 = make_float2(acc[mt][nt].x * sc, acc[mt][nt].y * sc);
            float2 v1 = make_float2(acc[mt][nt].z * sc, acc[mt][nt].w * sc);
            *(float2*)&Dp[(size_t)r0 * N_ + c0]       = v0;
            *(float2*)&Dp[(size_t)(r0 + 8) * N_ + c0] = v1;
            if (MODE == 1) {  // fp16 logits for softmax pass-1 stats
                *(__half2*)&Hp[(size_t)r0 * N_ + c0]       = __floats2half2_rn(v0.x, v0.y);
                *(__half2*)&Hp[(size_t)(r0 + 8) * N_ + c0] = __floats2half2_rn(v1.x, v1.y);
            }
        }
    }
}

// ============================================================================
// Softmax over i (axis=1) of W[b,i,j], in place.
// Pass 1 computes (m,l) from fp16 logits (g_w16); pass 2 exponentiates fp32
// logits and writes fp32 weights + fp16 weights (g_w16, overwriting logits).
// ============================================================================
__global__ __launch_bounds__(512, 2)
void softmax_kernel(float* __restrict__ w)
{
    const int b   = blockIdx.y;
    const int jl  = threadIdx.x & 63;
    const int seg = threadIdx.x >> 6;
    const int j   = blockIdx.x * 64 + jl;

    float*  Wb = w     + (size_t)b * N_ * N_;
    __half* Hb = g_w16 + (size_t)b * N_ * N_;
    const int I0 = seg * 256;

    float m = -CUDART_INF_F, l = 0.f;
    for (int i = I0; i < I0 + 256; i += 8) {
        float x[8];
#pragma unroll
        for (int u = 0; u < 8; u++) x[u] = __half2float(Hb[(size_t)(i + u) * N_ + j]);
        float cm = x[0];
#pragma unroll
        for (int u = 1; u < 8; u++) cm = fmaxf(cm, x[u]);
        float cl = 0.f;
#pragma unroll
        for (int u = 0; u < 8; u++) cl += __expf(x[u] - cm);
        const float nm = fmaxf(m, cm);
        l = l * __expf(m - nm) + cl * __expf(cm - nm);
        m = nm;
    }

    __shared__ float sm[8][64];
    __shared__ float sl[8][64];
    sm[seg][jl] = m;
    sl[seg][jl] = l;
    __syncthreads();

    __shared__ float fm_s[64], fl_s[64];
    if (seg == 0) {
        float fm = sm[0][jl], fl = sl[0][jl];
#pragma unroll
        for (int s = 1; s < 8; s++) {
            const float om = sm[s][jl], ol = sl[s][jl];
            const float nm = fmaxf(fm, om);
            fl = fl * __expf(fm - nm) + ol * __expf(om - nm);
            fm = nm;
        }
        fm_s[jl] = fm;
        fl_s[jl] = fl;
    }
    __syncthreads();

    const float fm  = fm_s[jl];
    const float inv = 1.f / fl_s[jl];
    for (int i = I0; i < I0 + 256; i += 8) {
        float x[8];
#pragma unroll
        for (int u = 0; u < 8; u++) x[u] = Wb[(size_t)(i + u) * N_ + j];
#pragma unroll
        for (int u = 0; u < 8; u++) {
            const float r = __expf(x[u] - fm) * inv;
            Wb[(size_t)(i + u) * N_ + j] = r;
            Hb[(size_t)(i + u) * N_ + j] = __float2half_rn(r);
        }
    }
}

// ============================================================================
extern "C" void kernel_launch(void* const* d_in, const int* in_sizes, int n_in,
                              void* d_out, int out_size)
{
    const float* q = (const float*)d_in[0];
    const float* k = (const float*)d_in[1];
    const float* v = (const float*)d_in[2];

    float* out = (float*)d_out;                        // [B, C, N]
    float* w   = (float*)d_out + (size_t)B_ * C_ * N_; // [B, N, N]

    dim3 gc((unsigned)(((size_t)B_ * C_ * N_) / 1024), 3);
    cvt16_all<<<gc, 256>>>(q, k, v);

    // GEMM1: W[i,j] = SCALE * sum_c K[c,i] Q[c,j]  (+ fp16 logits)
    dim3 g1(N_ / 128, N_ / 128, B_);   // (16,16,8)
    gemm_f16<1><<<g1, 256>>>(w);

    // softmax over i (fp16 stats pass, fp32 normalize, emits fp16 W)
    dim3 gs(N_ / 64, B_);              // (32,8)
    softmax_kernel<<<gs, 512>>>(w);

    // GEMM2: out[c,j] = sum_i V[c,i] W[i,j]
    dim3 g2(N_ / 128, C_ / 128, B_);   // (16,2,8)
    gemm_f16<2><<<g2, 256>>>(out);
}

// round 9
// speedup vs baseline: 1.2049x; 1.2049x over previous
#include <cuda_runtime.h>
#include <cuda_fp16.h>
#include <math_constants.h>
#include <cstdint>

#define B_ 8
#define C_ 256
#define N_ 2048
#define SCALE 0.0625f  // 1/sqrt(256)

// ------------------------- device scratch ----------------------------------
__device__ __align__(16) __half g_q16[(size_t)B_ * C_ * N_];
__device__ __align__(16) __half g_k16[(size_t)B_ * C_ * N_];
__device__ __align__(16) __half g_v16[(size_t)B_ * C_ * N_];
__device__ __align__(16) __half g_w16[(size_t)B_ * N_ * N_];
__device__ __align__(16) float  g_partl[(size_t)B_ * 16 * N_]; // per-i-tile col sums
__device__ __align__(16) float  g_invl[(size_t)B_ * N_];       // 1/L per column

// ------------------------------ PTX helpers --------------------------------
__device__ __forceinline__ uint32_t smem_u32(const void* p) {
    uint32_t a;
    asm("{ .reg .u64 t; cvta.to.shared.u64 t, %1; cvt.u32.u64 %0, t; }"
        : "=r"(a) : "l"(p));
    return a;
}
__device__ __forceinline__ void cp16(uint32_t dst, const void* src) {
    asm volatile("cp.async.cg.shared.global [%0], [%1], 16;" :: "r"(dst), "l"(src));
}
#define CP_COMMIT() asm volatile("cp.async.commit_group;" ::: "memory")
#define CP_WAIT2()  asm volatile("cp.async.wait_group 2;" ::: "memory")

#define LDSM4(r0, r1, r2, r3, a)                                               \
    asm volatile("ldmatrix.sync.aligned.m8n8.x4.shared.b16 {%0,%1,%2,%3},[%4];"\
                 : "=r"(r0), "=r"(r1), "=r"(r2), "=r"(r3) : "r"(a))
#define LDSM4T(r0, r1, r2, r3, a)                                              \
    asm volatile("ldmatrix.sync.aligned.m8n8.x4.trans.shared.b16 "             \
                 "{%0,%1,%2,%3},[%4];"                                         \
                 : "=r"(r0), "=r"(r1), "=r"(r2), "=r"(r3) : "r"(a))

__device__ __forceinline__ void mma_f16(float4& d, const uint32_t a[4],
                                        uint32_t b0, uint32_t b1) {
    asm volatile(
        "mma.sync.aligned.m16n8k16.row.col.f32.f16.f16.f32 "
        "{%0,%1,%2,%3}, {%4,%5,%6,%7}, {%8,%9}, {%0,%1,%2,%3};"
        : "+f"(d.x), "+f"(d.y), "+f"(d.z), "+f"(d.w)
        : "r"(a[0]), "r"(a[1]), "r"(a[2]), "r"(a[3]), "r"(b0), "r"(b1));
}

// ============================================================================
// fp32 -> fp16 convert, all three tensors in one launch.
// ============================================================================
__global__ __launch_bounds__(256)
void cvt16_all(const float* __restrict__ q, const float* __restrict__ k,
               const float* __restrict__ v)
{
    const float* s = (blockIdx.y == 0) ? q : (blockIdx.y == 1) ? k : v;
    __half* d = (blockIdx.y == 0) ? g_q16 : (blockIdx.y == 1) ? g_k16 : g_v16;
    size_t i = ((size_t)blockIdx.x * 256 + threadIdx.x) * 4;
    float4 x = *(const float4*)(s + i);
    *(__half2*)(d + i)     = __floats2half2_rn(x.x, x.y);
    *(__half2*)(d + i + 2) = __floats2half2_rn(x.z, x.w);
}

// ============================================================================
// fp16 GEMM (cp.async + ldmatrix + mma.m16n8k16).
//   MODE 1: W[b,i,j] = exp(SCALE * sum_c K(c,i) Q(c,j))  (unnormalized!)
//           + per-CTA column sums -> g_partl[b][i_tile][j]
//   MODE 2: out[b,c,j] = sum_i V(c,i) * W16(i,j)
// CTA 128x128, 256 thr = 8 warps (2x4), warp 64x32, BK=16, 4-stage cp.async.
// ============================================================================
template <int MODE>
__global__ __launch_bounds__(256, 2)
void gemm_f16(float* __restrict__ Dg)
{
    __shared__ __align__(256) uint8_t smem[4 * 8192];
    __shared__ float red[2][128];
    const uint32_t sb = smem_u32(smem);

    const __half* Ag = (MODE == 1) ? g_k16 : g_v16;
    const __half* Bg = (MODE == 1) ? g_q16 : g_w16;
    const size_t batchA = (size_t)C_ * N_;
    const size_t batchB = (MODE == 1) ? (size_t)C_ * N_ : (size_t)N_ * N_;
    const size_t batchD = (MODE == 1) ? (size_t)N_ * N_ : (size_t)C_ * N_;
    const int Ktot = (MODE == 1) ? C_ : N_;

    const int tid  = threadIdx.x;
    const int w    = tid >> 5;
    const int lane = tid & 31;
    const int qr   = lane >> 2;
    const int qc   = lane & 3;
    const int g2   = lane >> 3;
    const int tr   = lane & 7;
    const int wm   = (w >> 2) * 64;
    const int wn   = (w & 3) * 32;
    const int m0   = blockIdx.y * 128;
    const int j0   = blockIdx.x * 128;

    const __half* A  = Ag + (size_t)blockIdx.z * batchA;
    const __half* Bp = Bg + (size_t)blockIdx.z * batchB;
    float* Dp = Dg + (size_t)blockIdx.z * batchD;

    float4 acc[4][4];
#pragma unroll
    for (int mt = 0; mt < 4; mt++)
#pragma unroll
        for (int nt = 0; nt < 4; nt++)
            acc[mt][nt] = make_float4(0.f, 0.f, 0.f, 0.f);

    // ---- cp.async mapping ----
    const int brow = tid >> 4, bch = tid & 15;
    const uint32_t bdst = (uint32_t)brow * 256 + (uint32_t)((bch ^ (brow & 7)) << 4);
    const int arow2 = tid >> 1, ach2 = tid & 1;
    const uint32_t adst2 = (uint32_t)arow2 * 32 +
                           (uint32_t)((ach2 ^ ((arow2 >> 2) & 1)) << 4);

    auto issue = [&](int s) {
        const uint32_t bb = sb + (uint32_t)(s & 3) * 8192;
        const int k0 = s << 4;
        if (MODE == 1) {
            cp16(bb + bdst, A + (size_t)(k0 + brow) * N_ + m0 + bch * 8);
        } else {
            cp16(bb + adst2, A + (size_t)(m0 + arow2) * N_ + k0 + ach2 * 8);
        }
        cp16(bb + 4096 + bdst, Bp + (size_t)(k0 + brow) * N_ + j0 + bch * 8);
    };

    const int S = Ktot >> 4;
    issue(0); CP_COMMIT();
    issue(1); CP_COMMIT();
    issue(2); CP_COMMIT();

    // ---- ldmatrix address precompute ----
    uint32_t aoff[4], boff[2];
    if (MODE == 1) {
        const int kr = tr + ((g2 >> 1) << 3);
#pragma unroll
        for (int mt = 0; mt < 4; mt++) {
            const int ch = ((wm + mt * 16) >> 3) + (g2 & 1);
            aoff[mt] = (uint32_t)kr * 256 + (uint32_t)((ch ^ (kr & 7)) << 4);
        }
    } else {
#pragma unroll
        for (int mt = 0; mt < 4; mt++) {
            const int mr = wm + mt * 16 + tr + ((g2 & 1) << 3);
            const int ch = (g2 >> 1) ^ ((mr >> 2) & 1);
            aoff[mt] = (uint32_t)mr * 32 + (uint32_t)(ch << 4);
        }
    }
    {
        const int kr = tr + ((g2 & 1) << 3);
#pragma unroll
        for (int p = 0; p < 2; p++) {
            const int ch = ((wn + p * 16) >> 3) + (g2 >> 1);
            boff[p] = 4096u + (uint32_t)kr * 256 + (uint32_t)((ch ^ (kr & 7)) << 4);
        }
    }

#pragma unroll 1
    for (int s = 0; s < S; s++) {
        CP_WAIT2();
        __syncthreads();
        if (s + 3 < S) issue(s + 3);
        CP_COMMIT();

        const uint32_t bb = sb + (uint32_t)(s & 3) * 8192;

        uint32_t bf[2][4];
#pragma unroll
        for (int p = 0; p < 2; p++)
            LDSM4T(bf[p][0], bf[p][1], bf[p][2], bf[p][3], bb + boff[p]);

#pragma unroll
        for (int mt = 0; mt < 4; mt++) {
            uint32_t af[4];
            if (MODE == 1) { LDSM4T(af[0], af[1], af[2], af[3], bb + aoff[mt]); }
            else           { LDSM4 (af[0], af[1], af[2], af[3], bb + aoff[mt]); }
#pragma unroll
            for (int p = 0; p < 2; p++) {
                mma_f16(acc[mt][p * 2],     af, bf[p][0], bf[p][1]);
                mma_f16(acc[mt][p * 2 + 1], af, bf[p][2], bf[p][3]);
            }
        }
    }

    // ---------------- epilogue ----------------
    if (MODE == 2) {
#pragma unroll
        for (int mt = 0; mt < 4; mt++) {
            const int r0 = m0 + wm + mt * 16 + qr;
#pragma unroll
            for (int nt = 0; nt < 4; nt++) {
                const int c0 = j0 + wn + nt * 8 + qc * 2;
                *(float2*)&Dp[(size_t)r0 * N_ + c0] =
                    make_float2(acc[mt][nt].x, acc[mt][nt].y);
                *(float2*)&Dp[(size_t)(r0 + 8) * N_ + c0] =
                    make_float2(acc[mt][nt].z, acc[mt][nt].w);
            }
        }
    } else {
        // exp(scale * logit), store unnormalized weights, gather column sums
        float cs[4][2];
#pragma unroll
        for (int nt = 0; nt < 4; nt++) { cs[nt][0] = 0.f; cs[nt][1] = 0.f; }
#pragma unroll
        for (int mt = 0; mt < 4; mt++) {
            const int r0 = m0 + wm + mt * 16 + qr;
#pragma unroll
            for (int nt = 0; nt < 4; nt++) {
                const int c0 = j0 + wn + nt * 8 + qc * 2;
                float e0 = __expf(acc[mt][nt].x * SCALE);
                float e1 = __expf(acc[mt][nt].y * SCALE);
                float e2 = __expf(acc[mt][nt].z * SCALE);
                float e3 = __expf(acc[mt][nt].w * SCALE);
                *(float2*)&Dp[(size_t)r0 * N_ + c0]       = make_float2(e0, e1);
                *(float2*)&Dp[(size_t)(r0 + 8) * N_ + c0] = make_float2(e2, e3);
                cs[nt][0] += e0 + e2;
                cs[nt][1] += e1 + e3;
            }
        }
        // reduce over qr within warp (lane = qr*4 + qc)
#pragma unroll
        for (int nt = 0; nt < 4; nt++)
#pragma unroll
            for (int e = 0; e < 2; e++) {
                float v = cs[nt][e];
#pragma unroll
                for (int o = 16; o >= 4; o >>= 1)
                    v += __shfl_down_sync(0xffffffffu, v, o);
                cs[nt][e] = v;
            }
        if (qr == 0) {
#pragma unroll
            for (int nt = 0; nt < 4; nt++)
#pragma unroll
                for (int e = 0; e < 2; e++)
                    red[w >> 2][wn + nt * 8 + qc * 2 + e] = cs[nt][e];
        }
        __syncthreads();
        if (tid < 128) {
            g_partl[((size_t)blockIdx.z * 16 + blockIdx.y) * N_ + j0 + tid] =
                red[0][tid] + red[1][tid];
        }
    }
}

// ============================================================================
// reduce: L[b][j] = sum over 16 i-tiles; store 1/L.
// ============================================================================
__global__ __launch_bounds__(256)
void reduce_l()
{
    const int t = blockIdx.x * 256 + threadIdx.x;    // over B_*N_
    const int b = t >> 11, j = t & (N_ - 1);
    float s = 0.f;
#pragma unroll
    for (int it = 0; it < 16; it++)
        s += g_partl[((size_t)b * 16 + it) * N_ + j];
    g_invl[t] = 1.f / s;
}

// ============================================================================
// normalize: W *= 1/L[j] (fp32 in place) and emit fp16 copy for gemm2.
// ============================================================================
__global__ __launch_bounds__(256)
void normalize(float* __restrict__ w)
{
    size_t idx = ((size_t)blockIdx.x * 256 + threadIdx.x) * 4;
    const size_t b = idx >> 22;                      // / (N_*N_)
    const int j = (int)(idx & (N_ - 1));
    float4 x = *(float4*)(w + idx);
    const float4 iv = *(const float4*)(g_invl + b * N_ + j);
    x.x *= iv.x; x.y *= iv.y; x.z *= iv.z; x.w *= iv.w;
    *(float4*)(w + idx) = x;
    *(__half2*)(g_w16 + idx)     = __floats2half2_rn(x.x, x.y);
    *(__half2*)(g_w16 + idx + 2) = __floats2half2_rn(x.z, x.w);
}

// ============================================================================
extern "C" void kernel_launch(void* const* d_in, const int* in_sizes, int n_in,
                              void* d_out, int out_size)
{
    const float* q = (const float*)d_in[0];
    const float* k = (const float*)d_in[1];
    const float* v = (const float*)d_in[2];

    float* out = (float*)d_out;                        // [B, C, N]
    float* w   = (float*)d_out + (size_t)B_ * C_ * N_; // [B, N, N]

    dim3 gc((unsigned)(((size_t)B_ * C_ * N_) / 1024), 3);
    cvt16_all<<<gc, 256>>>(q, k, v);

    // GEMM1 + exp + partial column sums
    dim3 g1(N_ / 128, N_ / 128, B_);   // (16,16,8)
    gemm_f16<1><<<g1, 256>>>(w);

    reduce_l<<<(B_ * N_) / 256, 256>>>();

    normalize<<<(unsigned)(((size_t)B_ * N_ * N_) / 1024), 256>>>(w);

    // GEMM2: out[c,j] = sum_i V[c,i] W[i,j]
    dim3 g2(N_ / 128, C_ / 128, B_);   // (16,2,8)
    gemm_f16<2><<<g2, 256>>>(out);
}

// round 10
// speedup vs baseline: 1.3426x; 1.1143x over previous
#include <cuda_runtime.h>
#include <cuda_fp16.h>
#include <math_constants.h>
#include <cstdint>

#define B_ 8
#define C_ 256
#define N_ 2048
#define SCALE 0.0625f  // 1/sqrt(256)

// ------------------------- device scratch ----------------------------------
__device__ __align__(16) __half g_q16[(size_t)B_ * C_ * N_];
__device__ __align__(16) __half g_k16[(size_t)B_ * C_ * N_];
__device__ __align__(16) __half g_v16[(size_t)B_ * C_ * N_];
__device__ __align__(16) __half g_w16[(size_t)B_ * N_ * N_];  // unnormalized exp (E)
__device__ __align__(16) float  g_partl[(size_t)B_ * 16 * N_]; // per-i-tile col sums
__device__ __align__(16) float  g_invl[(size_t)B_ * N_];       // 1/L per column

// ------------------------------ PTX helpers --------------------------------
__device__ __forceinline__ uint32_t smem_u32(const void* p) {
    uint32_t a;
    asm("{ .reg .u64 t; cvta.to.shared.u64 t, %1; cvt.u32.u64 %0, t; }"
        : "=r"(a) : "l"(p));
    return a;
}
__device__ __forceinline__ void cp16(uint32_t dst, const void* src) {
    asm volatile("cp.async.cg.shared.global [%0], [%1], 16;" :: "r"(dst), "l"(src));
}
#define CP_COMMIT() asm volatile("cp.async.commit_group;" ::: "memory")
#define CP_WAIT2()  asm volatile("cp.async.wait_group 2;" ::: "memory")

#define LDSM4(r0, r1, r2, r3, a)                                               \
    asm volatile("ldmatrix.sync.aligned.m8n8.x4.shared.b16 {%0,%1,%2,%3},[%4];"\
                 : "=r"(r0), "=r"(r1), "=r"(r2), "=r"(r3) : "r"(a))
#define LDSM4T(r0, r1, r2, r3, a)                                              \
    asm volatile("ldmatrix.sync.aligned.m8n8.x4.trans.shared.b16 "             \
                 "{%0,%1,%2,%3},[%4];"                                         \
                 : "=r"(r0), "=r"(r1), "=r"(r2), "=r"(r3) : "r"(a))

__device__ __forceinline__ void mma_f16(float4& d, const uint32_t a[4],
                                        uint32_t b0, uint32_t b1) {
    asm volatile(
        "mma.sync.aligned.m16n8k16.row.col.f32.f16.f16.f32 "
        "{%0,%1,%2,%3}, {%4,%5,%6,%7}, {%8,%9}, {%0,%1,%2,%3};"
        : "+f"(d.x), "+f"(d.y), "+f"(d.z), "+f"(d.w)
        : "r"(a[0]), "r"(a[1]), "r"(a[2]), "r"(a[3]), "r"(b0), "r"(b1));
}

// ============================================================================
// fp32 -> fp16 convert, all three tensors in one launch.
// ============================================================================
__global__ __launch_bounds__(256)
void cvt16_all(const float* __restrict__ q, const float* __restrict__ k,
               const float* __restrict__ v)
{
    const float* s = (blockIdx.y == 0) ? q : (blockIdx.y == 1) ? k : v;
    __half* d = (blockIdx.y == 0) ? g_q16 : (blockIdx.y == 1) ? g_k16 : g_v16;
    size_t i = ((size_t)blockIdx.x * 256 + threadIdx.x) * 4;
    float4 x = *(const float4*)(s + i);
    *(__half2*)(d + i)     = __floats2half2_rn(x.x, x.y);
    *(__half2*)(d + i + 2) = __floats2half2_rn(x.z, x.w);
}

// ============================================================================
// fp16 GEMM (cp.async + ldmatrix + mma.m16n8k16).
//   MODE 1: E[b,i,j] = exp(SCALE * sum_c K(c,i) Q(c,j))  -> g_w16 (fp16 only)
//           + per-CTA column sums -> g_partl[b][i_tile][j]
//   MODE 2: out[b,c,j] = invl[b][j] * sum_i V(c,i) * E16(i,j)
// CTA 128x128, 256 thr = 8 warps (2x4), warp 64x32, BK=16, 4-stage cp.async.
// ============================================================================
template <int MODE>
__global__ __launch_bounds__(256, 2)
void gemm_f16(float* __restrict__ Dg)
{
    __shared__ __align__(256) uint8_t smem[4 * 8192];
    __shared__ float red[2][128];
    const uint32_t sb = smem_u32(smem);

    const __half* Ag = (MODE == 1) ? g_k16 : g_v16;
    const __half* Bg = (MODE == 1) ? g_q16 : g_w16;
    const size_t batchA = (size_t)C_ * N_;
    const size_t batchB = (MODE == 1) ? (size_t)C_ * N_ : (size_t)N_ * N_;
    const int Ktot = (MODE == 1) ? C_ : N_;

    const int tid  = threadIdx.x;
    const int w    = tid >> 5;
    const int lane = tid & 31;
    const int qr   = lane >> 2;
    const int qc   = lane & 3;
    const int g2   = lane >> 3;
    const int tr   = lane & 7;
    const int wm   = (w >> 2) * 64;
    const int wn   = (w & 3) * 32;
    const int m0   = blockIdx.y * 128;
    const int j0   = blockIdx.x * 128;

    const __half* A  = Ag + (size_t)blockIdx.z * batchA;
    const __half* Bp = Bg + (size_t)blockIdx.z * batchB;

    float4 acc[4][4];
#pragma unroll
    for (int mt = 0; mt < 4; mt++)
#pragma unroll
        for (int nt = 0; nt < 4; nt++)
            acc[mt][nt] = make_float4(0.f, 0.f, 0.f, 0.f);

    // ---- cp.async mapping ----
    const int brow = tid >> 4, bch = tid & 15;
    const uint32_t bdst = (uint32_t)brow * 256 + (uint32_t)((bch ^ (brow & 7)) << 4);
    const int arow2 = tid >> 1, ach2 = tid & 1;
    const uint32_t adst2 = (uint32_t)arow2 * 32 +
                           (uint32_t)((ach2 ^ ((arow2 >> 2) & 1)) << 4);

    auto issue = [&](int s) {
        const uint32_t bb = sb + (uint32_t)(s & 3) * 8192;
        const int k0 = s << 4;
        if (MODE == 1) {
            cp16(bb + bdst, A + (size_t)(k0 + brow) * N_ + m0 + bch * 8);
        } else {
            cp16(bb + adst2, A + (size_t)(m0 + arow2) * N_ + k0 + ach2 * 8);
        }
        cp16(bb + 4096 + bdst, Bp + (size_t)(k0 + brow) * N_ + j0 + bch * 8);
    };

    const int S = Ktot >> 4;
    issue(0); CP_COMMIT();
    issue(1); CP_COMMIT();
    issue(2); CP_COMMIT();

    // ---- ldmatrix address precompute ----
    uint32_t aoff[4], boff[2];
    if (MODE == 1) {
        const int kr = tr + ((g2 >> 1) << 3);
#pragma unroll
        for (int mt = 0; mt < 4; mt++) {
            const int ch = ((wm + mt * 16) >> 3) + (g2 & 1);
            aoff[mt] = (uint32_t)kr * 256 + (uint32_t)((ch ^ (kr & 7)) << 4);
        }
    } else {
#pragma unroll
        for (int mt = 0; mt < 4; mt++) {
            const int mr = wm + mt * 16 + tr + ((g2 & 1) << 3);
            const int ch = (g2 >> 1) ^ ((mr >> 2) & 1);
            aoff[mt] = (uint32_t)mr * 32 + (uint32_t)(ch << 4);
        }
    }
    {
        const int kr = tr + ((g2 & 1) << 3);
#pragma unroll
        for (int p = 0; p < 2; p++) {
            const int ch = ((wn + p * 16) >> 3) + (g2 >> 1);
            boff[p] = 4096u + (uint32_t)kr * 256 + (uint32_t)((ch ^ (kr & 7)) << 4);
        }
    }

#pragma unroll 1
    for (int s = 0; s < S; s++) {
        CP_WAIT2();
        __syncthreads();
        if (s + 3 < S) issue(s + 3);
        CP_COMMIT();

        const uint32_t bb = sb + (uint32_t)(s & 3) * 8192;

        uint32_t bf[2][4];
#pragma unroll
        for (int p = 0; p < 2; p++)
            LDSM4T(bf[p][0], bf[p][1], bf[p][2], bf[p][3], bb + boff[p]);

#pragma unroll
        for (int mt = 0; mt < 4; mt++) {
            uint32_t af[4];
            if (MODE == 1) { LDSM4T(af[0], af[1], af[2], af[3], bb + aoff[mt]); }
            else           { LDSM4 (af[0], af[1], af[2], af[3], bb + aoff[mt]); }
#pragma unroll
            for (int p = 0; p < 2; p++) {
                mma_f16(acc[mt][p * 2],     af, bf[p][0], bf[p][1]);
                mma_f16(acc[mt][p * 2 + 1], af, bf[p][2], bf[p][3]);
            }
        }
    }

    // ---------------- epilogue ----------------
    if (MODE == 2) {
        float* Dp = Dg + (size_t)blockIdx.z * ((size_t)C_ * N_);
        const float* ivp = g_invl + (size_t)blockIdx.z * N_;
#pragma unroll
        for (int mt = 0; mt < 4; mt++) {
            const int r0 = m0 + wm + mt * 16 + qr;
#pragma unroll
            for (int nt = 0; nt < 4; nt++) {
                const int c0 = j0 + wn + nt * 8 + qc * 2;
                const float2 iv = *(const float2*)&ivp[c0];
                *(float2*)&Dp[(size_t)r0 * N_ + c0] =
                    make_float2(acc[mt][nt].x * iv.x, acc[mt][nt].y * iv.y);
                *(float2*)&Dp[(size_t)(r0 + 8) * N_ + c0] =
                    make_float2(acc[mt][nt].z * iv.x, acc[mt][nt].w * iv.y);
            }
        }
    } else {
        // exp(scale*logit) -> fp16 E; column sums (fp32) -> partials
        __half* Hp = g_w16 + (size_t)blockIdx.z * ((size_t)N_ * N_);
        float cs[4][2];
#pragma unroll
        for (int nt = 0; nt < 4; nt++) { cs[nt][0] = 0.f; cs[nt][1] = 0.f; }
#pragma unroll
        for (int mt = 0; mt < 4; mt++) {
            const int r0 = m0 + wm + mt * 16 + qr;
#pragma unroll
            for (int nt = 0; nt < 4; nt++) {
                const int c0 = j0 + wn + nt * 8 + qc * 2;
                float e0 = __expf(acc[mt][nt].x * SCALE);
                float e1 = __expf(acc[mt][nt].y * SCALE);
                float e2 = __expf(acc[mt][nt].z * SCALE);
                float e3 = __expf(acc[mt][nt].w * SCALE);
                *(__half2*)&Hp[(size_t)r0 * N_ + c0]       = __floats2half2_rn(e0, e1);
                *(__half2*)&Hp[(size_t)(r0 + 8) * N_ + c0] = __floats2half2_rn(e2, e3);
                cs[nt][0] += e0 + e2;
                cs[nt][1] += e1 + e3;
            }
        }
#pragma unroll
        for (int nt = 0; nt < 4; nt++)
#pragma unroll
            for (int e = 0; e < 2; e++) {
                float v = cs[nt][e];
#pragma unroll
                for (int o = 16; o >= 4; o >>= 1)
                    v += __shfl_down_sync(0xffffffffu, v, o);
                cs[nt][e] = v;
            }
        if (qr == 0) {
#pragma unroll
            for (int nt = 0; nt < 4; nt++)
#pragma unroll
                for (int e = 0; e < 2; e++)
                    red[w >> 2][wn + nt * 8 + qc * 2 + e] = cs[nt][e];
        }
        __syncthreads();
        if (tid < 128) {
            g_partl[((size_t)blockIdx.z * 16 + blockIdx.y) * N_ + j0 + tid] =
                red[0][tid] + red[1][tid];
        }
    }
}

// ============================================================================
// reduce: L[b][j] = sum over 16 i-tiles; store 1/L.
// ============================================================================
__global__ __launch_bounds__(256)
void reduce_l()
{
    const int t = blockIdx.x * 256 + threadIdx.x;    // over B_*N_
    const int b = t >> 11, j = t & (N_ - 1);
    float s = 0.f;
#pragma unroll
    for (int it = 0; it < 16; it++)
        s += g_partl[((size_t)b * 16 + it) * N_ + j];
    g_invl[t] = 1.f / s;
}

// ============================================================================
// normalize: W_fp32[idx] = E16[idx] * invl[j]  (reads fp16, writes fp32)
// ============================================================================
__global__ __launch_bounds__(256)
void normalize(float* __restrict__ w)
{
    size_t idx = ((size_t)blockIdx.x * 256 + threadIdx.x) * 4;
    const size_t b = idx >> 22;                      // / (N_*N_)
    const int j = (int)(idx & (N_ - 1));
    const float4 iv = *(const float4*)(g_invl + b * N_ + j);
    __half2 e01 = *(const __half2*)(g_w16 + idx);
    __half2 e23 = *(const __half2*)(g_w16 + idx + 2);
    float2 f01 = __half22float2(e01);
    float2 f23 = __half22float2(e23);
    float4 x = make_float4(f01.x * iv.x, f01.y * iv.y, f23.x * iv.z, f23.y * iv.w);
    *(float4*)(w + idx) = x;
}

// ============================================================================
extern "C" void kernel_launch(void* const* d_in, const int* in_sizes, int n_in,
                              void* d_out, int out_size)
{
    const float* q = (const float*)d_in[0];
    const float* k = (const float*)d_in[1];
    const float* v = (const float*)d_in[2];

    float* out = (float*)d_out;                        // [B, C, N]
    float* w   = (float*)d_out + (size_t)B_ * C_ * N_; // [B, N, N]

    dim3 gc((unsigned)(((size_t)B_ * C_ * N_) / 1024), 3);
    cvt16_all<<<gc, 256>>>(q, k, v);

    // GEMM1 + exp -> fp16 E + partial column sums
    dim3 g1(N_ / 128, N_ / 128, B_);   // (16,16,8)
    gemm_f16<1><<<g1, 256>>>(nullptr);

    reduce_l<<<(B_ * N_) / 256, 256>>>();

    // W fp32 output = E16 * invl
    normalize<<<(unsigned)(((size_t)B_ * N_ * N_) / 1024), 256>>>(w);

    // GEMM2: out = (V @ E16) * invl
    dim3 g2(N_ / 128, C_ / 128, B_);   // (16,2,8)
    gemm_f16<2><<<g2, 256>>>(out);
}

// round 11
// speedup vs baseline: 1.4383x; 1.0713x over previous
#include <cuda_runtime.h>
#include <cuda_fp16.h>
#include <math_constants.h>
#include <cstdint>

#define B_ 8
#define C_ 256
#define N_ 2048
#define SCALE 0.0625f  // 1/sqrt(256)

// ------------------------- device scratch ----------------------------------
__device__ __align__(16) __half g_q16[(size_t)B_ * C_ * N_];
__device__ __align__(16) __half g_k16[(size_t)B_ * C_ * N_];
__device__ __align__(16) __half g_v16[(size_t)B_ * C_ * N_];
__device__ __align__(16) __half g_w16[(size_t)B_ * N_ * N_];  // unnormalized exp (E)
__device__ __align__(16) float  g_partl[(size_t)B_ * 16 * N_]; // per-i-tile col sums
__device__ __align__(16) float  g_invl[(size_t)B_ * N_];       // 1/L per column

// ------------------------------ PTX helpers --------------------------------
__device__ __forceinline__ uint32_t smem_u32(const void* p) {
    uint32_t a;
    asm("{ .reg .u64 t; cvta.to.shared.u64 t, %1; cvt.u32.u64 %0, t; }"
        : "=r"(a) : "l"(p));
    return a;
}
__device__ __forceinline__ void cp16(uint32_t dst, const void* src) {
    asm volatile("cp.async.cg.shared.global [%0], [%1], 16;" :: "r"(dst), "l"(src));
}
#define CP_COMMIT() asm volatile("cp.async.commit_group;" ::: "memory")
#define CP_WAIT2()  asm volatile("cp.async.wait_group 2;" ::: "memory")

#define LDSM4(r0, r1, r2, r3, a)                                               \
    asm volatile("ldmatrix.sync.aligned.m8n8.x4.shared.b16 {%0,%1,%2,%3},[%4];"\
                 : "=r"(r0), "=r"(r1), "=r"(r2), "=r"(r3) : "r"(a))
#define LDSM4T(r0, r1, r2, r3, a)                                              \
    asm volatile("ldmatrix.sync.aligned.m8n8.x4.trans.shared.b16 "             \
                 "{%0,%1,%2,%3},[%4];"                                         \
                 : "=r"(r0), "=r"(r1), "=r"(r2), "=r"(r3) : "r"(a))

__device__ __forceinline__ void mma_f16(float4& d, const uint32_t a[4],
                                        uint32_t b0, uint32_t b1) {
    asm volatile(
        "mma.sync.aligned.m16n8k16.row.col.f32.f16.f16.f32 "
        "{%0,%1,%2,%3}, {%4,%5,%6,%7}, {%8,%9}, {%0,%1,%2,%3};"
        : "+f"(d.x), "+f"(d.y), "+f"(d.z), "+f"(d.w)
        : "r"(a[0]), "r"(a[1]), "r"(a[2]), "r"(a[3]), "r"(b0), "r"(b1));
}

// ============================================================================
// fp32 -> fp16 convert, all three tensors in one launch.
// ============================================================================
__global__ __launch_bounds__(256)
void cvt16_all(const float* __restrict__ q, const float* __restrict__ k,
               const float* __restrict__ v)
{
    const float* s = (blockIdx.y == 0) ? q : (blockIdx.y == 1) ? k : v;
    __half* d = (blockIdx.y == 0) ? g_q16 : (blockIdx.y == 1) ? g_k16 : g_v16;
    size_t i = ((size_t)blockIdx.x * 256 + threadIdx.x) * 4;
    float4 x = *(const float4*)(s + i);
    *(__half2*)(d + i)     = __floats2half2_rn(x.x, x.y);
    *(__half2*)(d + i + 2) = __floats2half2_rn(x.z, x.w);
}

// ============================================================================
// fp16 GEMM (cp.async + ldmatrix + mma.m16n8k16).
//   MODE 1: E[b,i,j] = exp(SCALE * sum_c K(c,i) Q(c,j))  -> g_w16 (fp16)
//           + per-CTA column sums -> g_partl[b][i_tile][j]
//   MODE 2: out[b,c,j] = invl[b][j] * sum_i V(c,i) * E16(i,j)
//           + streams W[b,i,j] = E16(i,j) * invl[b][j] from its smem tiles
//             (c-tile 0 covers i stages 0..63, c-tile 1 covers 64..127)
// CTA 128x128, 256 thr = 8 warps (2x4), warp 64x32, BK=16, 4-stage cp.async.
// ============================================================================
template <int MODE>
__global__ __launch_bounds__(256, 2)
void gemm_f16(float* __restrict__ Dg, float* __restrict__ Wg)
{
    __shared__ __align__(256) uint8_t smem[4 * 8192];
    __shared__ float red[2][128];
    const uint32_t sb = smem_u32(smem);

    const __half* Ag = (MODE == 1) ? g_k16 : g_v16;
    const __half* Bg = (MODE == 1) ? g_q16 : g_w16;
    const size_t batchA = (size_t)C_ * N_;
    const size_t batchB = (MODE == 1) ? (size_t)C_ * N_ : (size_t)N_ * N_;
    const int Ktot = (MODE == 1) ? C_ : N_;

    const int tid  = threadIdx.x;
    const int w    = tid >> 5;
    const int lane = tid & 31;
    const int qr   = lane >> 2;
    const int qc   = lane & 3;
    const int g2   = lane >> 3;
    const int tr   = lane & 7;
    const int wm   = (w >> 2) * 64;
    const int wn   = (w & 3) * 32;
    const int m0   = blockIdx.y * 128;
    const int j0   = blockIdx.x * 128;

    const __half* A  = Ag + (size_t)blockIdx.z * batchA;
    const __half* Bp = Bg + (size_t)blockIdx.z * batchB;

    float4 acc[4][4];
#pragma unroll
    for (int mt = 0; mt < 4; mt++)
#pragma unroll
        for (int nt = 0; nt < 4; nt++)
            acc[mt][nt] = make_float4(0.f, 0.f, 0.f, 0.f);

    // ---- cp.async mapping ----
    const int brow = tid >> 4, bch = tid & 15;
    const uint32_t bdst = (uint32_t)brow * 256 + (uint32_t)((bch ^ (brow & 7)) << 4);
    const int arow2 = tid >> 1, ach2 = tid & 1;
    const uint32_t adst2 = (uint32_t)arow2 * 32 +
                           (uint32_t)((ach2 ^ ((arow2 >> 2) & 1)) << 4);

    auto issue = [&](int s) {
        const uint32_t bb = sb + (uint32_t)(s & 3) * 8192;
        const int k0 = s << 4;
        if (MODE == 1) {
            cp16(bb + bdst, A + (size_t)(k0 + brow) * N_ + m0 + bch * 8);
        } else {
            cp16(bb + adst2, A + (size_t)(m0 + arow2) * N_ + k0 + ach2 * 8);
        }
        cp16(bb + 4096 + bdst, Bp + (size_t)(k0 + brow) * N_ + j0 + bch * 8);
    };

    const int S = Ktot >> 4;
    issue(0); CP_COMMIT();
    issue(1); CP_COMMIT();
    issue(2); CP_COMMIT();

    // ---- MODE 2: invl preload + W-write setup ----
    float ivw[8];
    float* Wrow = nullptr;
    if (MODE == 2) {
        const float* ivp = g_invl + (size_t)blockIdx.z * N_ + j0 + bch * 8;
#pragma unroll
        for (int e = 0; e < 8; e++) ivw[e] = ivp[e];
        Wrow = Wg + (size_t)blockIdx.z * ((size_t)N_ * N_) + j0 + bch * 8;
    }

    // ---- ldmatrix address precompute ----
    uint32_t aoff[4], boff[2];
    if (MODE == 1) {
        const int kr = tr + ((g2 >> 1) << 3);
#pragma unroll
        for (int mt = 0; mt < 4; mt++) {
            const int ch = ((wm + mt * 16) >> 3) + (g2 & 1);
            aoff[mt] = (uint32_t)kr * 256 + (uint32_t)((ch ^ (kr & 7)) << 4);
        }
    } else {
#pragma unroll
        for (int mt = 0; mt < 4; mt++) {
            const int mr = wm + mt * 16 + tr + ((g2 & 1) << 3);
            const int ch = (g2 >> 1) ^ ((mr >> 2) & 1);
            aoff[mt] = (uint32_t)mr * 32 + (uint32_t)(ch << 4);
        }
    }
    {
        const int kr = tr + ((g2 & 1) << 3);
#pragma unroll
        for (int p = 0; p < 2; p++) {
            const int ch = ((wn + p * 16) >> 3) + (g2 >> 1);
            boff[p] = 4096u + (uint32_t)kr * 256 + (uint32_t)((ch ^ (kr & 7)) << 4);
        }
    }

#pragma unroll 1
    for (int s = 0; s < S; s++) {
        CP_WAIT2();
        __syncthreads();
        if (s + 3 < S) issue(s + 3);
        CP_COMMIT();

        const uint32_t bb = sb + (uint32_t)(s & 3) * 8192;

        uint32_t bf[2][4];
#pragma unroll
        for (int p = 0; p < 2; p++)
            LDSM4T(bf[p][0], bf[p][1], bf[p][2], bf[p][3], bb + boff[p]);

#pragma unroll
        for (int mt = 0; mt < 4; mt++) {
            uint32_t af[4];
            if (MODE == 1) { LDSM4T(af[0], af[1], af[2], af[3], bb + aoff[mt]); }
            else           { LDSM4 (af[0], af[1], af[2], af[3], bb + aoff[mt]); }
#pragma unroll
            for (int p = 0; p < 2; p++) {
                mma_f16(acc[mt][p * 2],     af, bf[p][0], bf[p][1]);
                mma_f16(acc[mt][p * 2 + 1], af, bf[p][2], bf[p][3]);
            }
        }

        // ---- MODE 2: stream W = E16 * invl from this stage's B tile ----
        if (MODE == 2) {
            if ((int)blockIdx.y == (s >= (S >> 1))) {
                uint4 raw = *(const uint4*)(smem + (uint32_t)(s & 3) * 8192 + 4096 + bdst);
                const __half2* h = (const __half2*)&raw;
                float2 f0 = __half22float2(h[0]);
                float2 f1 = __half22float2(h[1]);
                float2 f2 = __half22float2(h[2]);
                float2 f3 = __half22float2(h[3]);
                float4 o0 = make_float4(f0.x * ivw[0], f0.y * ivw[1],
                                        f1.x * ivw[2], f1.y * ivw[3]);
                float4 o1 = make_float4(f2.x * ivw[4], f2.y * ivw[5],
                                        f3.x * ivw[6], f3.y * ivw[7]);
                float* wp = Wrow + (size_t)(s * 16 + brow) * N_;
                *(float4*)wp       = o0;
                *(float4*)(wp + 4) = o1;
            }
        }
    }

    // ---------------- epilogue ----------------
    if (MODE == 2) {
        float* Dp = Dg + (size_t)blockIdx.z * ((size_t)C_ * N_);
        const float* ivp = g_invl + (size_t)blockIdx.z * N_;
#pragma unroll
        for (int mt = 0; mt < 4; mt++) {
            const int r0 = m0 + wm + mt * 16 + qr;
#pragma unroll
            for (int nt = 0; nt < 4; nt++) {
                const int c0 = j0 + wn + nt * 8 + qc * 2;
                const float2 iv = *(const float2*)&ivp[c0];
                *(float2*)&Dp[(size_t)r0 * N_ + c0] =
                    make_float2(acc[mt][nt].x * iv.x, acc[mt][nt].y * iv.y);
                *(float2*)&Dp[(size_t)(r0 + 8) * N_ + c0] =
                    make_float2(acc[mt][nt].z * iv.x, acc[mt][nt].w * iv.y);
            }
        }
    } else {
        // exp(scale*logit) -> fp16 E; column sums (fp32) -> partials
        __half* Hp = g_w16 + (size_t)blockIdx.z * ((size_t)N_ * N_);
        float cs[4][2];
#pragma unroll
        for (int nt = 0; nt < 4; nt++) { cs[nt][0] = 0.f; cs[nt][1] = 0.f; }
#pragma unroll
        for (int mt = 0; mt < 4; mt++) {
            const int r0 = m0 + wm + mt * 16 + qr;
#pragma unroll
            for (int nt = 0; nt < 4; nt++) {
                const int c0 = j0 + wn + nt * 8 + qc * 2;
                float e0 = __expf(acc[mt][nt].x * SCALE);
                float e1 = __expf(acc[mt][nt].y * SCALE);
                float e2 = __expf(acc[mt][nt].z * SCALE);
                float e3 = __expf(acc[mt][nt].w * SCALE);
                *(__half2*)&Hp[(size_t)r0 * N_ + c0]       = __floats2half2_rn(e0, e1);
                *(__half2*)&Hp[(size_t)(r0 + 8) * N_ + c0] = __floats2half2_rn(e2, e3);
                cs[nt][0] += e0 + e2;
                cs[nt][1] += e1 + e3;
            }
        }
#pragma unroll
        for (int nt = 0; nt < 4; nt++)
#pragma unroll
            for (int e = 0; e < 2; e++) {
                float v = cs[nt][e];
#pragma unroll
                for (int o = 16; o >= 4; o >>= 1)
                    v += __shfl_down_sync(0xffffffffu, v, o);
                cs[nt][e] = v;
            }
        if (qr == 0) {
#pragma unroll
            for (int nt = 0; nt < 4; nt++)
#pragma unroll
                for (int e = 0; e < 2; e++)
                    red[w >> 2][wn + nt * 8 + qc * 2 + e] = cs[nt][e];
        }
        __syncthreads();
        if (tid < 128) {
            g_partl[((size_t)blockIdx.z * 16 + blockIdx.y) * N_ + j0 + tid] =
                red[0][tid] + red[1][tid];
        }
    }
}

// ============================================================================
// reduce: L[b][j] = sum over 16 i-tiles; store 1/L.
// ============================================================================
__global__ __launch_bounds__(256)
void reduce_l()
{
    const int t = blockIdx.x * 256 + threadIdx.x;    // over B_*N_
    const int b = t >> 11, j = t & (N_ - 1);
    float s = 0.f;
#pragma unroll
    for (int it = 0; it < 16; it++)
        s += g_partl[((size_t)b * 16 + it) * N_ + j];
    g_invl[t] = 1.f / s;
}

// ============================================================================
extern "C" void kernel_launch(void* const* d_in, const int* in_sizes, int n_in,
                              void* d_out, int out_size)
{
    const float* q = (const float*)d_in[0];
    const float* k = (const float*)d_in[1];
    const float* v = (const float*)d_in[2];

    float* out = (float*)d_out;                        // [B, C, N]
    float* w   = (float*)d_out + (size_t)B_ * C_ * N_; // [B, N, N]

    dim3 gc((unsigned)(((size_t)B_ * C_ * N_) / 1024), 3);
    cvt16_all<<<gc, 256>>>(q, k, v);

    // GEMM1 + exp -> fp16 E + partial column sums
    dim3 g1(N_ / 128, N_ / 128, B_);   // (16,16,8)
    gemm_f16<1><<<g1, 256>>>(nullptr, nullptr);

    reduce_l<<<(B_ * N_) / 256, 256>>>();

    // GEMM2: out = (V @ E16) * invl, and streams W = E16 * invl
    dim3 g2(N_ / 128, C_ / 128, B_);   // (16,2,8)
    gemm_f16<2><<<g2, 256>>>(out, w);
}